// round 4
// baseline (speedup 1.0000x reference)
#include <cuda_runtime.h>
#include <math.h>

#define N_CI    2048
#define N_ROWS  8192
#define N_COLS  8192
#define N_EL    524288          // 8192 * 64
#define ROW_SPLITS 8
#define TILE_C  64
#define LSTR    40
#define LCAP    36

__device__ __align__(16) float g_y[N_EL];
__device__ __align__(16) float g_yn[N_EL];
__device__ __align__(16) float g_part[ROW_SPLITS * N_EL];
__device__ float g_psum[N_CI];
__device__ float g_psq[N_CI];
__device__ float g_stats[2];

__device__ __forceinline__ float gelu_tanh(float v) {
    const float c = 0.7978845608028654f;
    float t = tanhf(c * (v + 0.044715f * v * v * v));
    return 0.5f * v * (1.0f + t);
}

// ---------------------------------------------------------------------------
// K1: y[i,l,j] = sum_{k,m} Wi[i,j,k,l,m] * x[i,m,k]; gelu; LN partials.
// ---------------------------------------------------------------------------
__global__ void __launch_bounds__(256) k1_capsule(const float* __restrict__ x,
                                                  const float* __restrict__ Wi) {
    __shared__ float4 xs4[64];
    __shared__ float s_sum, s_sq;
    int tid = threadIdx.x;
    int i = blockIdx.x;
    if (tid == 0) { s_sum = 0.f; s_sq = 0.f; }
    {
        int k = tid >> 2, m = tid & 3;
        ((float*)xs4)[tid] = x[(size_t)i * 256 + m * 64 + k];
    }
    __syncthreads();

    int w = tid >> 5, lane = tid & 31;
    int l = lane & 3, kq = lane >> 2;
    const float4* wbase = (const float4*)(Wi + (size_t)i * 65536);
    float ls = 0.f, ls2 = 0.f;

    #pragma unroll 1
    for (int jj = 0; jj < 8; jj++) {
        int j = w * 8 + jj;
        const float4* wp = wbase + (size_t)j * 256 + lane;
        float acc = 0.f;
        #pragma unroll
        for (int r = 0; r < 8; r++) {
            float4 wv = wp[r * 32];
            float4 xv = xs4[r * 8 + kq];
            acc = fmaf(wv.x, xv.x, acc);
            acc = fmaf(wv.y, xv.y, acc);
            acc = fmaf(wv.z, xv.z, acc);
            acc = fmaf(wv.w, xv.w, acc);
        }
        acc += __shfl_xor_sync(0xffffffffu, acc, 4);
        acc += __shfl_xor_sync(0xffffffffu, acc, 8);
        acc += __shfl_xor_sync(0xffffffffu, acc, 16);
        float g = gelu_tanh(acc);
        if (lane < 4) {
            g_y[((size_t)i * 4 + l) * 64 + j] = g;
            ls += g;
            ls2 += g * g;
        }
    }
    if (lane < 4) {
        atomicAdd(&s_sum, ls);
        atomicAdd(&s_sq, ls2);
    }
    __syncthreads();
    if (tid == 0) { g_psum[i] = s_sum; g_psq[i] = s_sq; }
}

// ---------------------------------------------------------------------------
// K2: reduce partials -> mu, rsig (1 CTA, fp64)
// ---------------------------------------------------------------------------
__global__ void k2_stats() {
    __shared__ double sh[256], sh2[256];
    int tid = threadIdx.x;
    double a = 0.0, b = 0.0;
    for (int i = tid; i < N_CI; i += 256) {
        a += (double)g_psum[i];
        b += (double)g_psq[i];
    }
    sh[tid] = a; sh2[tid] = b;
    __syncthreads();
    for (int s = 128; s > 0; s >>= 1) {
        if (tid < s) { sh[tid] += sh[tid + s]; sh2[tid] += sh2[tid + s]; }
        __syncthreads();
    }
    if (tid == 0) {
        double mu = sh[0] / (double)N_EL;
        double var = sh2[0] / (double)N_EL - mu * mu;
        g_stats[0] = (float)mu;
        g_stats[1] = (float)(1.0 / sqrt(var + 1e-6));
    }
}

// ---------------------------------------------------------------------------
// K2b: yn = (y - mu)*rsig*scale + bias   (float4)
// ---------------------------------------------------------------------------
__global__ void __launch_bounds__(256) k2b_norm(const float* __restrict__ sc,
                                                 const float* __restrict__ bi) {
    int idx = blockIdx.x * 256 + threadIdx.x;
    float mu = g_stats[0], rs = g_stats[1];
    float4 v = ((const float4*)g_y)[idx];
    float4 s = ((const float4*)sc)[idx];
    float4 b = ((const float4*)bi)[idx];
    float4 o;
    o.x = (v.x - mu) * rs * s.x + b.x;
    o.y = (v.y - mu) * rs * s.y + b.y;
    o.z = (v.z - mu) * rs * s.z + b.z;
    o.w = (v.w - mu) * rs * s.w + b.w;
    ((float4*)g_yn)[idx] = o;
}

// ---------------------------------------------------------------------------
// K3: out[col,m] = sum_row Co[row,col]*yn[row,m].
// Grid (128 col-tiles x 64 cols, 8 row-splits x 1024 rows), 256 threads.
// Per 128-row chunk:
//  stage:  yn chunk -> smem (32 KB).
//  scan:   warps 0-1 only; lane owns ONE column for all 128 rows (row-major
//          LDG.32, warp = 128B coalesced). Appends nonzero row idx to a
//          contiguous per-col list, stride 40B -> <=2-way bank conflicts.
//          No merge pass needed.
//  replay: 8 warps x 8 cols, warp-uniform 4-wide list walk; lanes cover m
//          (float2) -> conflict-free LDS.64, 2 FADD per nonzero.
// ---------------------------------------------------------------------------
__global__ void __launch_bounds__(256, 4) k3_route(const float* __restrict__ Co) {
    __shared__ float yn_s[128 * 64];                     // 32 KB
    __shared__ __align__(4) unsigned char lists[TILE_C * LSTR];
    __shared__ int cnt_s[TILE_C];
    int tid = threadIdx.x, w = tid >> 5, lane = tid & 31;
    int colbase = blockIdx.x * TILE_C;
    int rb0 = blockIdx.y * 1024;

    float2 acc[8];
    #pragma unroll
    for (int c = 0; c < 8; c++) { acc[c].x = 0.f; acc[c].y = 0.f; }

    for (int ch = 0; ch < 8; ch++) {
        int rowbase = rb0 + ch * 128;
        __syncthreads();
        // stage yn chunk (128 rows x 64 floats)
        {
            const float4* src = ((const float4*)g_yn) + (size_t)rowbase * 16;
            float4* dst = (float4*)yn_s;
            #pragma unroll
            for (int ii = 0; ii < 8; ii++) dst[tid + ii * 256] = src[tid + ii * 256];
        }

        // scan: warps 0-1, lane owns col (w*32 + lane), all 128 rows
        if (w < 2) {
            int cl = w * 32 + lane;
            const float* cop = Co + (size_t)rowbase * 8192 + colbase + cl;
            unsigned char* lp = lists + cl * LSTR;
            int n = 0;
            #pragma unroll 1
            for (int r = 0; r < 128; r += 8) {
                float v0 = __ldg(cop + (size_t)(r + 0) * 8192);
                float v1 = __ldg(cop + (size_t)(r + 1) * 8192);
                float v2 = __ldg(cop + (size_t)(r + 2) * 8192);
                float v3 = __ldg(cop + (size_t)(r + 3) * 8192);
                float v4 = __ldg(cop + (size_t)(r + 4) * 8192);
                float v5 = __ldg(cop + (size_t)(r + 5) * 8192);
                float v6 = __ldg(cop + (size_t)(r + 6) * 8192);
                float v7 = __ldg(cop + (size_t)(r + 7) * 8192);
                if (v0 != 0.f && n < LCAP) lp[n++] = (unsigned char)(r + 0);
                if (v1 != 0.f && n < LCAP) lp[n++] = (unsigned char)(r + 1);
                if (v2 != 0.f && n < LCAP) lp[n++] = (unsigned char)(r + 2);
                if (v3 != 0.f && n < LCAP) lp[n++] = (unsigned char)(r + 3);
                if (v4 != 0.f && n < LCAP) lp[n++] = (unsigned char)(r + 4);
                if (v5 != 0.f && n < LCAP) lp[n++] = (unsigned char)(r + 5);
                if (v6 != 0.f && n < LCAP) lp[n++] = (unsigned char)(r + 6);
                if (v7 != 0.f && n < LCAP) lp[n++] = (unsigned char)(r + 7);
            }
            cnt_s[cl] = n;
        }
        __syncthreads();

        // replay: warp w owns cols w*8 .. w*8+7, warp-uniform
        #pragma unroll
        for (int c = 0; c < 8; c++) {
            int cc = w * 8 + c;
            int n = cnt_s[cc];
            const unsigned char* ll = lists + cc * LSTR;
            #pragma unroll 1
            for (int t = 0; t < n; t += 4) {
                unsigned rr = *(const unsigned*)(ll + t);
                int r0 = (rr      ) & 255;
                int r1 = (rr >>  8) & 255;
                int r2 = (rr >> 16) & 255;
                int r3 = (rr >> 24) & 255;
                float2 a0 = *(const float2*)&yn_s[r0 * 64 + lane * 2];
                acc[c].x += a0.x; acc[c].y += a0.y;
                if (t + 1 < n) {
                    float2 a1 = *(const float2*)&yn_s[r1 * 64 + lane * 2];
                    acc[c].x += a1.x; acc[c].y += a1.y;
                }
                if (t + 2 < n) {
                    float2 a2 = *(const float2*)&yn_s[r2 * 64 + lane * 2];
                    acc[c].x += a2.x; acc[c].y += a2.y;
                }
                if (t + 3 < n) {
                    float2 a3 = *(const float2*)&yn_s[r3 * 64 + lane * 2];
                    acc[c].x += a3.x; acc[c].y += a3.y;
                }
            }
        }
    }

    // write exclusive partial tile
    float* pb = g_part + (size_t)blockIdx.y * N_EL;
    #pragma unroll
    for (int c = 0; c < 8; c++) {
        size_t col = (size_t)colbase + w * 8 + c;
        *(float2*)&pb[col * 64 + lane * 2] = acc[c];
    }
}

// ---------------------------------------------------------------------------
// K4: out = sum over 8 partials (float4)
// ---------------------------------------------------------------------------
__global__ void __launch_bounds__(256) k4_reduce(float* __restrict__ out) {
    int idx = blockIdx.x * 256 + threadIdx.x;
    float4 a = ((const float4*)g_part)[idx];
    #pragma unroll
    for (int s = 1; s < ROW_SPLITS; s++) {
        float4 b = ((const float4*)(g_part + (size_t)s * N_EL))[idx];
        a.x += b.x; a.y += b.y; a.z += b.z; a.w += b.w;
    }
    ((float4*)out)[idx] = a;
}

extern "C" void kernel_launch(void* const* d_in, const int* in_sizes, int n_in,
                              void* d_out, int out_size) {
    const float* x  = (const float*)d_in[0];
    const float* Wi = (const float*)d_in[1];
    const float* sc = (const float*)d_in[2];
    const float* bi = (const float*)d_in[3];
    const float* Co = (const float*)d_in[4];
    float* out = (float*)d_out;

    k1_capsule<<<N_CI, 256>>>(x, Wi);
    k2_stats<<<1, 256>>>();
    k2b_norm<<<512, 256>>>(sc, bi);
    dim3 g3(128, ROW_SPLITS);
    k3_route<<<g3, 256>>>(Co);
    k4_reduce<<<512, 256>>>(out);
}

// round 5
// speedup vs baseline: 1.0715x; 1.0715x over previous
#include <cuda_runtime.h>
#include <math.h>

#define N_CI    2048
#define N_ROWS  8192
#define N_COLS  8192
#define N_EL    524288          // 8192 * 64
#define ROW_SPLITS 8
#define N_RW    256             // row words (8192/32)

__device__ __align__(16) float g_y[N_EL];
__device__ __align__(16) float g_yn[N_EL];
__device__ __align__(16) float g_part[ROW_SPLITS * N_EL];
__device__ __align__(16) unsigned g_mask[N_RW * N_COLS];   // 8 MB
__device__ float g_psum[N_CI];
__device__ float g_psq[N_CI];
__device__ float g_stats[2];

__device__ __forceinline__ float gelu_tanh(float v) {
    const float c = 0.7978845608028654f;
    float t = tanhf(c * (v + 0.044715f * v * v * v));
    return 0.5f * v * (1.0f + t);
}

// ---------------------------------------------------------------------------
// K1: y[i,l,j] = sum_{k,m} Wi[i,j,k,l,m] * x[i,m,k]; gelu; LN partials.
// ---------------------------------------------------------------------------
__global__ void __launch_bounds__(256) k1_capsule(const float* __restrict__ x,
                                                  const float* __restrict__ Wi) {
    __shared__ float4 xs4[64];
    __shared__ float s_sum, s_sq;
    int tid = threadIdx.x;
    int i = blockIdx.x;
    if (tid == 0) { s_sum = 0.f; s_sq = 0.f; }
    {
        int k = tid >> 2, m = tid & 3;
        ((float*)xs4)[tid] = x[(size_t)i * 256 + m * 64 + k];
    }
    __syncthreads();

    int w = tid >> 5, lane = tid & 31;
    int l = lane & 3, kq = lane >> 2;
    const float4* wbase = (const float4*)(Wi + (size_t)i * 65536);
    float ls = 0.f, ls2 = 0.f;

    #pragma unroll 1
    for (int jj = 0; jj < 8; jj++) {
        int j = w * 8 + jj;
        const float4* wp = wbase + (size_t)j * 256 + lane;
        float acc = 0.f;
        #pragma unroll
        for (int r = 0; r < 8; r++) {
            float4 wv = wp[r * 32];
            float4 xv = xs4[r * 8 + kq];
            acc = fmaf(wv.x, xv.x, acc);
            acc = fmaf(wv.y, xv.y, acc);
            acc = fmaf(wv.z, xv.z, acc);
            acc = fmaf(wv.w, xv.w, acc);
        }
        acc += __shfl_xor_sync(0xffffffffu, acc, 4);
        acc += __shfl_xor_sync(0xffffffffu, acc, 8);
        acc += __shfl_xor_sync(0xffffffffu, acc, 16);
        float g = gelu_tanh(acc);
        if (lane < 4) {
            g_y[((size_t)i * 4 + l) * 64 + j] = g;
            ls += g;
            ls2 += g * g;
        }
    }
    if (lane < 4) {
        atomicAdd(&s_sum, ls);
        atomicAdd(&s_sq, ls2);
    }
    __syncthreads();
    if (tid == 0) { g_psum[i] = s_sum; g_psq[i] = s_sq; }
}

// ---------------------------------------------------------------------------
// K2: reduce partials -> mu, rsig (1 CTA, fp64)
// ---------------------------------------------------------------------------
__global__ void k2_stats() {
    __shared__ double sh[256], sh2[256];
    int tid = threadIdx.x;
    double a = 0.0, b = 0.0;
    for (int i = tid; i < N_CI; i += 256) {
        a += (double)g_psum[i];
        b += (double)g_psq[i];
    }
    sh[tid] = a; sh2[tid] = b;
    __syncthreads();
    for (int s = 128; s > 0; s >>= 1) {
        if (tid < s) { sh[tid] += sh[tid + s]; sh2[tid] += sh2[tid + s]; }
        __syncthreads();
    }
    if (tid == 0) {
        double mu = sh[0] / (double)N_EL;
        double var = sh2[0] / (double)N_EL - mu * mu;
        g_stats[0] = (float)mu;
        g_stats[1] = (float)(1.0 / sqrt(var + 1e-6));
    }
}

// ---------------------------------------------------------------------------
// K2b: yn = (y - mu)*rsig*scale + bias   (float4)
// ---------------------------------------------------------------------------
__global__ void __launch_bounds__(256) k2b_norm(const float* __restrict__ sc,
                                                 const float* __restrict__ bi) {
    int idx = blockIdx.x * 256 + threadIdx.x;
    float mu = g_stats[0], rs = g_stats[1];
    float4 v = ((const float4*)g_y)[idx];
    float4 s = ((const float4*)sc)[idx];
    float4 b = ((const float4*)bi)[idx];
    float4 o;
    o.x = (v.x - mu) * rs * s.x + b.x;
    o.y = (v.y - mu) * rs * s.y + b.y;
    o.z = (v.z - mu) * rs * s.z + b.z;
    o.w = (v.w - mu) * rs * s.w + b.w;
    ((float4*)g_yn)[idx] = o;
}

// ---------------------------------------------------------------------------
// K3a: build column bitmasks from Co. Pure streaming (268 MB read, 8 MB write).
// g_mask[rw*8192 + col] bit r = (Co[rw*32+r, col] != 0).
// Warp handles 32x32 blocks: 32 coalesced row loads (two 16-deep batches for
// MLP), 32 ballots (bits = cols/lanes), register bit-transpose, coalesced store.
// Grid (8 col-slabs x 256 row-words), 256 threads.
// ---------------------------------------------------------------------------
__global__ void __launch_bounds__(256) k3a_mask(const float* __restrict__ Co) {
    int w = threadIdx.x >> 5, lane = threadIdx.x & 31;
    int rowbase = blockIdx.y * 32;
    unsigned rw_words[32];
    #pragma unroll 1
    for (int b = 0; b < 4; b++) {
        int col32 = blockIdx.x * 1024 + w * 128 + b * 32;
        const float* cp = Co + (size_t)rowbase * 8192 + col32 + lane;
        #pragma unroll 1
        for (int h = 0; h < 2; h++) {
            float v[16];
            #pragma unroll
            for (int r = 0; r < 16; r++)
                v[r] = __ldg(cp + (size_t)(h * 16 + r) * 8192);
            #pragma unroll
            for (int r = 0; r < 16; r++)
                rw_words[h * 16 + r] = __ballot_sync(0xffffffffu, v[r] != 0.f);
        }
        unsigned out = 0;
        #pragma unroll
        for (int r = 0; r < 32; r++)
            out |= ((rw_words[r] >> lane) & 1u) << r;
        g_mask[(size_t)blockIdx.y * 8192 + col32 + lane] = out;
    }
}

// ---------------------------------------------------------------------------
// K3b: out[col,m] = sum_{row: bit set} yn[row,m].
// Grid (128 col-tiles x 64 cols, 8 row-splits x 1024 rows), 256 threads.
// Per 128-row chunk: stage yn (32 KB) + 256 mask words (coalesced). Warp owns
// 8 cols; walks set bits warp-uniformly (ffs/clear), lanes cover m (float2).
// No scanning, no lists — all 8 warps replay continuously.
// ---------------------------------------------------------------------------
__global__ void __launch_bounds__(256) k3b_route() {
    __shared__ float yn_s[128 * 64];        // 32 KB
    __shared__ unsigned mask_s[256];        // 4 rw x 64 cols
    int tid = threadIdx.x, w = tid >> 5, lane = tid & 31;
    int colbase = blockIdx.x * 64;
    int rw0 = blockIdx.y * 32;              // row-word base of this split

    float2 acc[8];
    #pragma unroll
    for (int c = 0; c < 8; c++) { acc[c].x = 0.f; acc[c].y = 0.f; }

    #pragma unroll 1
    for (int ch = 0; ch < 8; ch++) {
        int rowbase = (rw0 + ch * 4) * 32;
        __syncthreads();
        {
            const float4* src = ((const float4*)g_yn) + (size_t)rowbase * 16;
            float4* dst = (float4*)yn_s;
            #pragma unroll
            for (int ii = 0; ii < 8; ii++) dst[tid + ii * 256] = src[tid + ii * 256];
        }
        {
            int rw = tid >> 6, c = tid & 63;
            mask_s[tid] = g_mask[(size_t)(rw0 + ch * 4 + rw) * 8192 + colbase + c];
        }
        __syncthreads();

        #pragma unroll
        for (int c = 0; c < 8; c++) {
            int cc = w * 8 + c;
            #pragma unroll
            for (int rw = 0; rw < 4; rw++) {
                unsigned m = mask_s[rw * 64 + cc];
                int base = rw * 32;
                while (m) {
                    int r = __ffs(m) - 1;
                    m &= m - 1u;
                    float2 a = *(const float2*)&yn_s[(base + r) * 64 + lane * 2];
                    acc[c].x += a.x;
                    acc[c].y += a.y;
                }
            }
        }
    }

    float* pb = g_part + (size_t)blockIdx.y * N_EL;
    #pragma unroll
    for (int c = 0; c < 8; c++) {
        size_t col = (size_t)colbase + w * 8 + c;
        *(float2*)&pb[col * 64 + lane * 2] = acc[c];
    }
}

// ---------------------------------------------------------------------------
// K4: out = sum over 8 partials (float4)
// ---------------------------------------------------------------------------
__global__ void __launch_bounds__(256) k4_reduce(float* __restrict__ out) {
    int idx = blockIdx.x * 256 + threadIdx.x;
    float4 a = ((const float4*)g_part)[idx];
    #pragma unroll
    for (int s = 1; s < ROW_SPLITS; s++) {
        float4 b = ((const float4*)(g_part + (size_t)s * N_EL))[idx];
        a.x += b.x; a.y += b.y; a.z += b.z; a.w += b.w;
    }
    ((float4*)out)[idx] = a;
}

extern "C" void kernel_launch(void* const* d_in, const int* in_sizes, int n_in,
                              void* d_out, int out_size) {
    const float* x  = (const float*)d_in[0];
    const float* Wi = (const float*)d_in[1];
    const float* sc = (const float*)d_in[2];
    const float* bi = (const float*)d_in[3];
    const float* Co = (const float*)d_in[4];
    float* out = (float*)d_out;

    dim3 ga(8, 256);
    k3a_mask<<<ga, 256>>>(Co);
    k1_capsule<<<N_CI, 256>>>(x, Wi);
    k2_stats<<<1, 256>>>();
    k2b_norm<<<512, 256>>>(sc, bi);
    dim3 gb(128, ROW_SPLITS);
    k3b_route<<<gb, 256>>>();
    k4_reduce<<<512, 256>>>(out);
}

// round 7
// speedup vs baseline: 1.5009x; 1.4008x over previous
#include <cuda_runtime.h>
#include <cuda_bf16.h>
#include <math.h>
#include <stdint.h>

#define N_CI    2048
#define N_EL    524288          // 8192 * 64
#define KSPLIT  2
#define KHALF   4096
#define KC      32
#define NCH     (KHALF / KC)    // 128 chunks
#define CO_LD   136             // Co tile row stride (bf16 elems), 17x16B units
#define YN_LD   40              // ynT tile row stride, 5x16B units

__device__ __align__(16) float g_y[N_EL];
__device__ __align__(16) __nv_bfloat16 g_ynT_hi[64 * 8192];   // [m][row]
__device__ __align__(16) __nv_bfloat16 g_ynT_lo[64 * 8192];
__device__ __align__(16) float g_part[KSPLIT * N_EL];
__device__ float g_psum[N_CI];
__device__ float g_psq[N_CI];
__device__ float g_stats[2];

__device__ __forceinline__ float gelu_tanh(float v) {
    const float c = 0.7978845608028654f;
    float t = tanhf(c * (v + 0.044715f * v * v * v));
    return 0.5f * v * (1.0f + t);
}

// ===========================================================================
// K1: y[i,l,j] = sum_{k,m} Wi[i,j,k,l,m] * x[i,m,k]; gelu; LN partials.
// ===========================================================================
__global__ void __launch_bounds__(256) k1_capsule(const float* __restrict__ x,
                                                  const float* __restrict__ Wi) {
    __shared__ float4 xs4[64];
    __shared__ float s_sum, s_sq;
    int tid = threadIdx.x;
    int i = blockIdx.x;
    if (tid == 0) { s_sum = 0.f; s_sq = 0.f; }
    {
        int k = tid >> 2, m = tid & 3;
        ((float*)xs4)[tid] = x[(size_t)i * 256 + m * 64 + k];
    }
    __syncthreads();

    int w = tid >> 5, lane = tid & 31;
    int l = lane & 3, kq = lane >> 2;
    const float4* wbase = (const float4*)(Wi + (size_t)i * 65536);
    float ls = 0.f, ls2 = 0.f;

    #pragma unroll 1
    for (int jj = 0; jj < 8; jj++) {
        int j = w * 8 + jj;
        const float4* wp = wbase + (size_t)j * 256 + lane;
        float acc = 0.f;
        #pragma unroll
        for (int r = 0; r < 8; r++) {
            float4 wv = wp[r * 32];
            float4 xv = xs4[r * 8 + kq];
            acc = fmaf(wv.x, xv.x, acc);
            acc = fmaf(wv.y, xv.y, acc);
            acc = fmaf(wv.z, xv.z, acc);
            acc = fmaf(wv.w, xv.w, acc);
        }
        acc += __shfl_xor_sync(0xffffffffu, acc, 4);
        acc += __shfl_xor_sync(0xffffffffu, acc, 8);
        acc += __shfl_xor_sync(0xffffffffu, acc, 16);
        float g = gelu_tanh(acc);
        if (lane < 4) {
            g_y[((size_t)i * 4 + l) * 64 + j] = g;
            ls += g;
            ls2 += g * g;
        }
    }
    if (lane < 4) {
        atomicAdd(&s_sum, ls);
        atomicAdd(&s_sq, ls2);
    }
    __syncthreads();
    if (tid == 0) { g_psum[i] = s_sum; g_psq[i] = s_sq; }
}

// ===========================================================================
// K2: reduce partials -> mu, rsig (1 CTA, fp64)
// ===========================================================================
__global__ void k2_stats() {
    __shared__ double sh[256], sh2[256];
    int tid = threadIdx.x;
    double a = 0.0, b = 0.0;
    for (int i = tid; i < N_CI; i += 256) {
        a += (double)g_psum[i];
        b += (double)g_psq[i];
    }
    sh[tid] = a; sh2[tid] = b;
    __syncthreads();
    for (int s = 128; s > 0; s >>= 1) {
        if (tid < s) { sh[tid] += sh[tid + s]; sh2[tid] += sh2[tid + s]; }
        __syncthreads();
    }
    if (tid == 0) {
        double mu = sh[0] / (double)N_EL;
        double var = sh2[0] / (double)N_EL - mu * mu;
        g_stats[0] = (float)mu;
        g_stats[1] = (float)(1.0 / sqrt(var + 1e-6));
    }
}

// ===========================================================================
// K2b: normalize + hi/lo bf16 split + transpose into ynT_hi/lo[m][row].
// ===========================================================================
__global__ void __launch_bounds__(256) k2b_normT(const float* __restrict__ sc,
                                                  const float* __restrict__ bi) {
    __shared__ __nv_bfloat16 shi[64 * 65];
    __shared__ __nv_bfloat16 slo[64 * 65];
    int tid = threadIdx.x;
    int r0 = blockIdx.x * 64;
    float mu = g_stats[0], rs = g_stats[1];

    #pragma unroll
    for (int it = 0; it < 16; it++) {
        int idx = tid + it * 256;
        int r = idx >> 6, m = idx & 63;
        size_t gi = (size_t)(r0 + r) * 64 + m;
        float val = (g_y[gi] - mu) * rs * sc[gi] + bi[gi];
        __nv_bfloat16 hi = __float2bfloat16(val);
        __nv_bfloat16 lo = __float2bfloat16(val - __bfloat162float(hi));
        shi[m * 65 + r] = hi;
        slo[m * 65 + r] = lo;
    }
    __syncthreads();

    int w = tid >> 5, lane = tid & 31;
    #pragma unroll 1
    for (int m = w; m < 64; m += 8) {
        __nv_bfloat162 ph, pl;
        ph.x = shi[m * 65 + lane * 2]; ph.y = shi[m * 65 + lane * 2 + 1];
        pl.x = slo[m * 65 + lane * 2]; pl.y = slo[m * 65 + lane * 2 + 1];
        *((__nv_bfloat162*)(g_ynT_hi + (size_t)m * 8192 + r0) + lane) = ph;
        *((__nv_bfloat162*)(g_ynT_lo + (size_t)m * 8192 + r0) + lane) = pl;
    }
}

// ===========================================================================
// mma helpers (legacy HMMA path — compiles for plain sm_103)
// ===========================================================================
__device__ __forceinline__ void ldsm4(uint32_t& r0, uint32_t& r1, uint32_t& r2,
                                      uint32_t& r3, const void* p) {
    uint32_t a = (uint32_t)__cvta_generic_to_shared(p);
    asm volatile("ldmatrix.sync.aligned.m8n8.x4.shared.b16 {%0,%1,%2,%3}, [%4];"
                 : "=r"(r0), "=r"(r1), "=r"(r2), "=r"(r3) : "r"(a));
}
__device__ __forceinline__ void ldsm4t(uint32_t& r0, uint32_t& r1, uint32_t& r2,
                                       uint32_t& r3, const void* p) {
    uint32_t a = (uint32_t)__cvta_generic_to_shared(p);
    asm volatile("ldmatrix.sync.aligned.m8n8.x4.trans.shared.b16 {%0,%1,%2,%3}, [%4];"
                 : "=r"(r0), "=r"(r1), "=r"(r2), "=r"(r3) : "r"(a));
}
__device__ __forceinline__ void mma16816(float* d, uint32_t a0, uint32_t a1,
                                         uint32_t a2, uint32_t a3,
                                         uint32_t b0, uint32_t b1) {
    asm volatile(
        "mma.sync.aligned.m16n8k16.row.col.f32.bf16.bf16.f32 "
        "{%0,%1,%2,%3}, {%4,%5,%6,%7}, {%8,%9}, {%0,%1,%2,%3};"
        : "+f"(d[0]), "+f"(d[1]), "+f"(d[2]), "+f"(d[3])
        : "r"(a0), "r"(a1), "r"(a2), "r"(a3), "r"(b0), "r"(b1));
}

// ===========================================================================
// K3: out_part[n,m] = sum_k ynT[m',k]*Co[k,n] via mma.sync bf16 (hi/lo split).
// Grid (64 col-tiles x 128 n, 2 k-splits x 4096). 256 threads.
// A = ynT tile [m'=128][k=32] (row-major, ldmatrix.x4).
// B = Co tile [k=32][n=128] fp32->bf16 (col-major B via ldmatrix.x4.trans).
// Warp w owns n in [w*16, w*16+16). D: 8 m-tiles x 2 n-tiles x 4 = 64 regs.
// Double-buffered smem, one-chunk LDG prefetch. Epilogue: hi+lo combine.
// ===========================================================================
__global__ void __launch_bounds__(256) k3_gemm(const float* __restrict__ Co) {
    __shared__ __align__(16) __nv_bfloat16 co_s[2][KC][CO_LD];     // 17.4 KB
    __shared__ __align__(16) __nv_bfloat16 yn_s[2][128][YN_LD];    // 20.5 KB
    int tid = threadIdx.x, w = tid >> 5, lane = tid & 31;
    int colbase = blockIdx.x * 128;
    int k_org = blockIdx.y * KHALF;

    // load mappings
    int ck = tid >> 3, cseg = (tid & 7) * 16;     // Co: k-row, n offset (16 floats)
    int ym = tid >> 1, yseg = (tid & 1) * 16;     // ynT: m' row, k offset (16 bf16)
    const __nv_bfloat16* yptr = (ym < 64 ? g_ynT_hi + (size_t)ym * 8192
                                         : g_ynT_lo + (size_t)(ym - 64) * 8192)
                                + k_org + yseg;
    const float4* cptr = (const float4*)(Co + (size_t)(k_org + ck) * 8192 + colbase + cseg);

    float4 cr[4];
    uint4  yr[2];

    auto LOAD = [&](int ch) {
        const float4* p = cptr + (size_t)ch * KC * 2048;
        cr[0] = __ldg(p); cr[1] = __ldg(p + 1); cr[2] = __ldg(p + 2); cr[3] = __ldg(p + 3);
        const uint4* q = (const uint4*)(yptr + ch * KC);
        yr[0] = __ldg(q); yr[1] = __ldg(q + 1);
    };
    auto STORE = [&](int buf) {
        uint32_t wd[8];
        #pragma unroll
        for (int j = 0; j < 4; j++) {
            asm("cvt.rn.bf16x2.f32 %0, %1, %2;" : "=r"(wd[2 * j])     : "f"(cr[j].y), "f"(cr[j].x));
            asm("cvt.rn.bf16x2.f32 %0, %1, %2;" : "=r"(wd[2 * j + 1]) : "f"(cr[j].w), "f"(cr[j].z));
        }
        uint4* cd = (uint4*)&co_s[buf][ck][cseg];
        cd[0] = make_uint4(wd[0], wd[1], wd[2], wd[3]);
        cd[1] = make_uint4(wd[4], wd[5], wd[6], wd[7]);
        uint4* yd = (uint4*)&yn_s[buf][ym][yseg];
        yd[0] = yr[0]; yd[1] = yr[1];
    };

    float d[8][2][4];
    #pragma unroll
    for (int mt = 0; mt < 8; mt++)
        #pragma unroll
        for (int nt = 0; nt < 2; nt++)
            #pragma unroll
            for (int v = 0; v < 4; v++) d[mt][nt][v] = 0.f;

    int q = lane >> 3, r8 = lane & 7;
    int arow = (q & 1) * 8 + r8, acol = (q >> 1) * 8;   // quad mapping

    LOAD(0); STORE(0);
    LOAD(1);
    __syncthreads();

    #pragma unroll 1
    for (int ch = 0; ch < NCH; ch++) {
        int buf = ch & 1;
        #pragma unroll
        for (int kk = 0; kk < 2; kk++) {
            uint32_t b0, b1, b2, b3;
            // B x4.trans: stored rows k = kk*16 + (q&1)*8 + r8, col = w*16 + (q>>1)*8
            ldsm4t(b0, b1, b2, b3, &co_s[buf][kk * 16 + arow][w * 16 + acol]);
            #pragma unroll
            for (int mt = 0; mt < 8; mt++) {
                uint32_t a0, a1, a2, a3;
                // A x4: rows m' = mt*16 + (q&1)*8 + r8, col k = kk*16 + (q>>1)*8
                ldsm4(a0, a1, a2, a3, &yn_s[buf][mt * 16 + arow][kk * 16 + acol]);
                mma16816(d[mt][0], a0, a1, a2, a3, b0, b1);
                mma16816(d[mt][1], a0, a1, a2, a3, b2, b3);
            }
        }
        __syncthreads();
        if (ch + 1 < NCH) {
            STORE(buf ^ 1);
            if (ch + 2 < NCH) LOAD(ch + 2);
        }
        __syncthreads();
    }

    // epilogue: combine hi (mt 0-3) + lo (mt 4-7), write k-split partial
    float* pb = g_part + (size_t)blockIdx.y * N_EL;
    int er = lane >> 2, ec = (lane & 3) * 2;
    #pragma unroll
    for (int mt = 0; mt < 4; mt++) {
        #pragma unroll
        for (int nt = 0; nt < 2; nt++) {
            int n = colbase + w * 16 + nt * 8 + ec;
            int m = mt * 16 + er;
            float v0 = d[mt][nt][0] + d[mt + 4][nt][0];
            float v1 = d[mt][nt][1] + d[mt + 4][nt][1];
            float v2 = d[mt][nt][2] + d[mt + 4][nt][2];
            float v3 = d[mt][nt][3] + d[mt + 4][nt][3];
            pb[(size_t)n * 64 + m]           = v0;
            pb[(size_t)(n + 1) * 64 + m]     = v1;
            pb[(size_t)n * 64 + m + 8]       = v2;
            pb[(size_t)(n + 1) * 64 + m + 8] = v3;
        }
    }
}

// ===========================================================================
// K4: out = part0 + part1 (float4)
// ===========================================================================
__global__ void __launch_bounds__(256) k4_reduce(float* __restrict__ out) {
    int idx = blockIdx.x * 256 + threadIdx.x;
    float4 a = ((const float4*)g_part)[idx];
    float4 b = ((const float4*)(g_part + N_EL))[idx];
    a.x += b.x; a.y += b.y; a.z += b.z; a.w += b.w;
    ((float4*)out)[idx] = a;
}

extern "C" void kernel_launch(void* const* d_in, const int* in_sizes, int n_in,
                              void* d_out, int out_size) {
    const float* x  = (const float*)d_in[0];
    const float* Wi = (const float*)d_in[1];
    const float* sc = (const float*)d_in[2];
    const float* bi = (const float*)d_in[3];
    const float* Co = (const float*)d_in[4];
    float* out = (float*)d_out;

    k1_capsule<<<N_CI, 256>>>(x, Wi);
    k2_stats<<<1, 256>>>();
    k2b_normT<<<128, 256>>>(sc, bi);
    dim3 g3(64, KSPLIT);
    k3_gemm<<<g3, 256>>>(Co);
    k4_reduce<<<512, 256>>>(out);
}

// round 8
// speedup vs baseline: 1.6196x; 1.0791x over previous
#include <cuda_runtime.h>
#include <cuda_bf16.h>
#include <math.h>
#include <stdint.h>

#define N_CI    2048
#define N_EL    524288          // 8192 * 64
#define KSPLIT  4
#define KQ      2048            // K per split
#define KC      32
#define NCH     (KQ / KC)       // 64 chunks
#define NBUF    (KSPLIT * 2)    // partial buffers (x hi/lo)
#define CO_LD   136             // Co tile row stride (bf16 elems)
#define YN_LD   40              // ynT tile row stride

__device__ __align__(16) float g_y[N_EL];
__device__ __align__(16) __nv_bfloat16 g_ynT_hi[64 * 8192];   // [m][row]
__device__ __align__(16) __nv_bfloat16 g_ynT_lo[64 * 8192];
__device__ __align__(16) float g_part[NBUF * N_EL];
__device__ float g_psum[N_CI];
__device__ float g_psq[N_CI];
__device__ float g_stats[2];

__device__ __forceinline__ float gelu_tanh(float v) {
    const float c = 0.7978845608028654f;
    float t = tanhf(c * (v + 0.044715f * v * v * v));
    return 0.5f * v * (1.0f + t);
}

// ===========================================================================
// K1: y[i,l,j] = sum_{k,m} Wi[i,j,k,l,m] * x[i,m,k]; gelu; LN partials.
// ===========================================================================
__global__ void __launch_bounds__(256) k1_capsule(const float* __restrict__ x,
                                                  const float* __restrict__ Wi) {
    __shared__ float4 xs4[64];
    __shared__ float s_sum, s_sq;
    int tid = threadIdx.x;
    int i = blockIdx.x;
    if (tid == 0) { s_sum = 0.f; s_sq = 0.f; }
    {
        int k = tid >> 2, m = tid & 3;
        ((float*)xs4)[tid] = x[(size_t)i * 256 + m * 64 + k];
    }
    __syncthreads();

    int w = tid >> 5, lane = tid & 31;
    int l = lane & 3, kq = lane >> 2;
    const float4* wbase = (const float4*)(Wi + (size_t)i * 65536);
    float ls = 0.f, ls2 = 0.f;

    #pragma unroll 1
    for (int jj = 0; jj < 8; jj++) {
        int j = w * 8 + jj;
        const float4* wp = wbase + (size_t)j * 256 + lane;
        float acc = 0.f;
        #pragma unroll
        for (int r = 0; r < 8; r++) {
            float4 wv = wp[r * 32];
            float4 xv = xs4[r * 8 + kq];
            acc = fmaf(wv.x, xv.x, acc);
            acc = fmaf(wv.y, xv.y, acc);
            acc = fmaf(wv.z, xv.z, acc);
            acc = fmaf(wv.w, xv.w, acc);
        }
        acc += __shfl_xor_sync(0xffffffffu, acc, 4);
        acc += __shfl_xor_sync(0xffffffffu, acc, 8);
        acc += __shfl_xor_sync(0xffffffffu, acc, 16);
        float g = gelu_tanh(acc);
        if (lane < 4) {
            g_y[((size_t)i * 4 + l) * 64 + j] = g;
            ls += g;
            ls2 += g * g;
        }
    }
    if (lane < 4) {
        atomicAdd(&s_sum, ls);
        atomicAdd(&s_sq, ls2);
    }
    __syncthreads();
    if (tid == 0) { g_psum[i] = s_sum; g_psq[i] = s_sq; }
}

// ===========================================================================
// K2: reduce partials -> mu, rsig (1 CTA, fp64)
// ===========================================================================
__global__ void k2_stats() {
    __shared__ double sh[256], sh2[256];
    int tid = threadIdx.x;
    double a = 0.0, b = 0.0;
    for (int i = tid; i < N_CI; i += 256) {
        a += (double)g_psum[i];
        b += (double)g_psq[i];
    }
    sh[tid] = a; sh2[tid] = b;
    __syncthreads();
    for (int s = 128; s > 0; s >>= 1) {
        if (tid < s) { sh[tid] += sh[tid + s]; sh2[tid] += sh2[tid + s]; }
        __syncthreads();
    }
    if (tid == 0) {
        double mu = sh[0] / (double)N_EL;
        double var = sh2[0] / (double)N_EL - mu * mu;
        g_stats[0] = (float)mu;
        g_stats[1] = (float)(1.0 / sqrt(var + 1e-6));
    }
}

// ===========================================================================
// K2b: normalize + hi/lo bf16 split + transpose into ynT_hi/lo[m][row].
// ===========================================================================
__global__ void __launch_bounds__(256) k2b_normT(const float* __restrict__ sc,
                                                  const float* __restrict__ bi) {
    __shared__ __nv_bfloat16 shi[64 * 65];
    __shared__ __nv_bfloat16 slo[64 * 65];
    int tid = threadIdx.x;
    int r0 = blockIdx.x * 64;
    float mu = g_stats[0], rs = g_stats[1];

    #pragma unroll
    for (int it = 0; it < 16; it++) {
        int idx = tid + it * 256;
        int r = idx >> 6, m = idx & 63;
        size_t gi = (size_t)(r0 + r) * 64 + m;
        float val = (g_y[gi] - mu) * rs * sc[gi] + bi[gi];
        __nv_bfloat16 hi = __float2bfloat16(val);
        __nv_bfloat16 lo = __float2bfloat16(val - __bfloat162float(hi));
        shi[m * 65 + r] = hi;
        slo[m * 65 + r] = lo;
    }
    __syncthreads();

    int w = tid >> 5, lane = tid & 31;
    #pragma unroll 1
    for (int m = w; m < 64; m += 8) {
        __nv_bfloat162 ph, pl;
        ph.x = shi[m * 65 + lane * 2]; ph.y = shi[m * 65 + lane * 2 + 1];
        pl.x = slo[m * 65 + lane * 2]; pl.y = slo[m * 65 + lane * 2 + 1];
        *((__nv_bfloat162*)(g_ynT_hi + (size_t)m * 8192 + r0) + lane) = ph;
        *((__nv_bfloat162*)(g_ynT_lo + (size_t)m * 8192 + r0) + lane) = pl;
    }
}

// ===========================================================================
// mma helpers (legacy HMMA path)
// ===========================================================================
__device__ __forceinline__ void ldsm4(uint32_t& r0, uint32_t& r1, uint32_t& r2,
                                      uint32_t& r3, const void* p) {
    uint32_t a = (uint32_t)__cvta_generic_to_shared(p);
    asm volatile("ldmatrix.sync.aligned.m8n8.x4.shared.b16 {%0,%1,%2,%3}, [%4];"
                 : "=r"(r0), "=r"(r1), "=r"(r2), "=r"(r3) : "r"(a));
}
__device__ __forceinline__ void ldsm4t(uint32_t& r0, uint32_t& r1, uint32_t& r2,
                                       uint32_t& r3, const void* p) {
    uint32_t a = (uint32_t)__cvta_generic_to_shared(p);
    asm volatile("ldmatrix.sync.aligned.m8n8.x4.trans.shared.b16 {%0,%1,%2,%3}, [%4];"
                 : "=r"(r0), "=r"(r1), "=r"(r2), "=r"(r3) : "r"(a));
}
__device__ __forceinline__ void mma16816(float* d, uint32_t a0, uint32_t a1,
                                         uint32_t a2, uint32_t a3,
                                         uint32_t b0, uint32_t b1) {
    asm volatile(
        "mma.sync.aligned.m16n8k16.row.col.f32.bf16.bf16.f32 "
        "{%0,%1,%2,%3}, {%4,%5,%6,%7}, {%8,%9}, {%0,%1,%2,%3};"
        : "+f"(d[0]), "+f"(d[1]), "+f"(d[2]), "+f"(d[3])
        : "r"(a0), "r"(a1), "r"(a2), "r"(a3), "r"(b0), "r"(b1));
}

// ===========================================================================
// K3: out_part[n,m] = sum_k ynT[m',k]*Co[k,n] via mma.sync bf16 (hi/lo split).
// Grid (64 col-tiles x 128 n, 4 k-splits x 2048). 256 threads, 2 CTAs/SM.
// Warp grid 2(m-group: hi/lo) x 4(n-group of 32): per kk each warp does
// 4 A-ldsm + 2 B-ldsm for 16 MMAs (ldsm/mma 0.375 vs 0.56 before).
// Warp writes its group's partial to buffer (ksplit*2 + mgroup); K4 sums 8.
// ===========================================================================
__global__ void __launch_bounds__(256, 2) k3_gemm(const float* __restrict__ Co) {
    __shared__ __align__(16) __nv_bfloat16 co_s[2][KC][CO_LD];
    __shared__ __align__(16) __nv_bfloat16 yn_s[2][128][YN_LD];
    int tid = threadIdx.x, w = tid >> 5, lane = tid & 31;
    int wm = w & 1, wn = w >> 1;                  // m-group (0=hi,1=lo), n-group
    int colbase = blockIdx.x * 128;
    int k_org = blockIdx.y * KQ;

    // load mappings (same tiling as R7)
    int ck = tid >> 3, cseg = (tid & 7) * 16;
    int ym = tid >> 1, yseg = (tid & 1) * 16;
    const __nv_bfloat16* yptr = (ym < 64 ? g_ynT_hi + (size_t)ym * 8192
                                         : g_ynT_lo + (size_t)(ym - 64) * 8192)
                                + k_org + yseg;
    const float4* cptr = (const float4*)(Co + (size_t)(k_org + ck) * 8192 + colbase + cseg);

    float4 cr[4];
    uint4  yr[2];

    auto LOAD = [&](int ch) {
        const float4* p = cptr + (size_t)ch * KC * 2048;
        cr[0] = __ldg(p); cr[1] = __ldg(p + 1); cr[2] = __ldg(p + 2); cr[3] = __ldg(p + 3);
        const uint4* q = (const uint4*)(yptr + ch * KC);
        yr[0] = __ldg(q); yr[1] = __ldg(q + 1);
    };
    auto STORE = [&](int buf) {
        uint32_t wd[8];
        #pragma unroll
        for (int j = 0; j < 4; j++) {
            asm("cvt.rn.bf16x2.f32 %0, %1, %2;" : "=r"(wd[2 * j])     : "f"(cr[j].y), "f"(cr[j].x));
            asm("cvt.rn.bf16x2.f32 %0, %1, %2;" : "=r"(wd[2 * j + 1]) : "f"(cr[j].w), "f"(cr[j].z));
        }
        uint4* cd = (uint4*)&co_s[buf][ck][cseg];
        cd[0] = make_uint4(wd[0], wd[1], wd[2], wd[3]);
        cd[1] = make_uint4(wd[4], wd[5], wd[6], wd[7]);
        uint4* yd = (uint4*)&yn_s[buf][ym][yseg];
        yd[0] = yr[0]; yd[1] = yr[1];
    };

    float d[4][4][4];                             // [mt][nt][v]
    #pragma unroll
    for (int mt = 0; mt < 4; mt++)
        #pragma unroll
        for (int nt = 0; nt < 4; nt++)
            #pragma unroll
            for (int v = 0; v < 4; v++) d[mt][nt][v] = 0.f;

    int q = lane >> 3, r8 = lane & 7;
    int arow = (q & 1) * 8 + r8, acol = (q >> 1) * 8;

    LOAD(0); STORE(0);
    LOAD(1);
    __syncthreads();

    #pragma unroll 1
    for (int ch = 0; ch < NCH; ch++) {
        int buf = ch & 1;
        #pragma unroll
        for (int kk = 0; kk < 2; kk++) {
            uint32_t b[8];
            ldsm4t(b[0], b[1], b[2], b[3], &co_s[buf][kk * 16 + arow][wn * 32 + acol]);
            ldsm4t(b[4], b[5], b[6], b[7], &co_s[buf][kk * 16 + arow][wn * 32 + 16 + acol]);
            #pragma unroll
            for (int mt = 0; mt < 4; mt++) {
                uint32_t a0, a1, a2, a3;
                ldsm4(a0, a1, a2, a3, &yn_s[buf][wm * 64 + mt * 16 + arow][kk * 16 + acol]);
                mma16816(d[mt][0], a0, a1, a2, a3, b[0], b[1]);
                mma16816(d[mt][1], a0, a1, a2, a3, b[2], b[3]);
                mma16816(d[mt][2], a0, a1, a2, a3, b[4], b[5]);
                mma16816(d[mt][3], a0, a1, a2, a3, b[6], b[7]);
            }
        }
        __syncthreads();
        if (ch + 1 < NCH) {
            STORE(buf ^ 1);
            if (ch + 2 < NCH) LOAD(ch + 2);
        }
        __syncthreads();
    }

    // epilogue: write this warp's (hi or lo) partial to its own buffer
    float* pb = g_part + (size_t)(blockIdx.y * 2 + wm) * N_EL;
    int er = lane >> 2, ec = (lane & 3) * 2;
    #pragma unroll
    for (int mt = 0; mt < 4; mt++) {
        #pragma unroll
        for (int nt = 0; nt < 4; nt++) {
            int n = colbase + wn * 32 + nt * 8 + ec;
            int m = mt * 16 + er;
            pb[(size_t)n * 64 + m]           = d[mt][nt][0];
            pb[(size_t)(n + 1) * 64 + m]     = d[mt][nt][1];
            pb[(size_t)n * 64 + m + 8]       = d[mt][nt][2];
            pb[(size_t)(n + 1) * 64 + m + 8] = d[mt][nt][3];
        }
    }
}

// ===========================================================================
// K4: out = sum of 8 partial buffers (float4)
// ===========================================================================
__global__ void __launch_bounds__(256) k4_reduce(float* __restrict__ out) {
    int idx = blockIdx.x * 256 + threadIdx.x;
    float4 a = ((const float4*)g_part)[idx];
    #pragma unroll
    for (int s = 1; s < NBUF; s++) {
        float4 b = ((const float4*)(g_part + (size_t)s * N_EL))[idx];
        a.x += b.x; a.y += b.y; a.z += b.z; a.w += b.w;
    }
    ((float4*)out)[idx] = a;
}

extern "C" void kernel_launch(void* const* d_in, const int* in_sizes, int n_in,
                              void* d_out, int out_size) {
    const float* x  = (const float*)d_in[0];
    const float* Wi = (const float*)d_in[1];
    const float* sc = (const float*)d_in[2];
    const float* bi = (const float*)d_in[3];
    const float* Co = (const float*)d_in[4];
    float* out = (float*)d_out;

    k1_capsule<<<N_CI, 256>>>(x, Wi);
    k2_stats<<<1, 256>>>();
    k2b_normT<<<128, 256>>>(sc, bi);
    dim3 g3(64, KSPLIT);
    k3_gemm<<<g3, 256>>>(Co);
    k4_reduce<<<512, 256>>>(out);
}

// round 9
// speedup vs baseline: 1.6411x; 1.0133x over previous
#include <cuda_runtime.h>
#include <cuda_fp16.h>
#include <math.h>
#include <stdint.h>

#define N_CI    2048
#define N_EL    524288          // 8192 * 64
#define KSPLIT  4
#define KQ      2048            // K per split
#define KC      32
#define NCH     (KQ / KC)       // 64 chunks
#define CO_LD   136             // Co tile row stride (fp16 elems)
#define YN_LD   40              // ynT tile row stride

__device__ __align__(16) float g_y[N_EL];
__device__ __align__(16) __half g_ynT[64 * 8192];         // [m][row], fp16
__device__ __align__(16) float g_part[KSPLIT * N_EL];
__device__ float g_psum[N_CI];
__device__ float g_psq[N_CI];
__device__ float g_stats[2];

__device__ __forceinline__ float gelu_tanh(float v) {
    const float c = 0.7978845608028654f;
    float t = tanhf(c * (v + 0.044715f * v * v * v));
    return 0.5f * v * (1.0f + t);
}

// ===========================================================================
// K1: y[i,l,j] = sum_{k,m} Wi[i,j,k,l,m] * x[i,m,k]; gelu; LN partials.
// ===========================================================================
__global__ void __launch_bounds__(256) k1_capsule(const float* __restrict__ x,
                                                  const float* __restrict__ Wi) {
    __shared__ float4 xs4[64];
    __shared__ float s_sum, s_sq;
    int tid = threadIdx.x;
    int i = blockIdx.x;
    if (tid == 0) { s_sum = 0.f; s_sq = 0.f; }
    {
        int k = tid >> 2, m = tid & 3;
        ((float*)xs4)[tid] = x[(size_t)i * 256 + m * 64 + k];
    }
    __syncthreads();

    int w = tid >> 5, lane = tid & 31;
    int l = lane & 3, kq = lane >> 2;
    const float4* wbase = (const float4*)(Wi + (size_t)i * 65536);
    float ls = 0.f, ls2 = 0.f;

    #pragma unroll 1
    for (int jj = 0; jj < 8; jj++) {
        int j = w * 8 + jj;
        const float4* wp = wbase + (size_t)j * 256 + lane;
        float acc = 0.f;
        #pragma unroll
        for (int r = 0; r < 8; r++) {
            float4 wv = wp[r * 32];
            float4 xv = xs4[r * 8 + kq];
            acc = fmaf(wv.x, xv.x, acc);
            acc = fmaf(wv.y, xv.y, acc);
            acc = fmaf(wv.z, xv.z, acc);
            acc = fmaf(wv.w, xv.w, acc);
        }
        acc += __shfl_xor_sync(0xffffffffu, acc, 4);
        acc += __shfl_xor_sync(0xffffffffu, acc, 8);
        acc += __shfl_xor_sync(0xffffffffu, acc, 16);
        float g = gelu_tanh(acc);
        if (lane < 4) {
            g_y[((size_t)i * 4 + l) * 64 + j] = g;
            ls += g;
            ls2 += g * g;
        }
    }
    if (lane < 4) {
        atomicAdd(&s_sum, ls);
        atomicAdd(&s_sq, ls2);
    }
    __syncthreads();
    if (tid == 0) { g_psum[i] = s_sum; g_psq[i] = s_sq; }
}

// ===========================================================================
// K2: reduce partials -> mu, rsig (1 CTA, fp64)
// ===========================================================================
__global__ void k2_stats() {
    __shared__ double sh[256], sh2[256];
    int tid = threadIdx.x;
    double a = 0.0, b = 0.0;
    for (int i = tid; i < N_CI; i += 256) {
        a += (double)g_psum[i];
        b += (double)g_psq[i];
    }
    sh[tid] = a; sh2[tid] = b;
    __syncthreads();
    for (int s = 128; s > 0; s >>= 1) {
        if (tid < s) { sh[tid] += sh[tid + s]; sh2[tid] += sh2[tid + s]; }
        __syncthreads();
    }
    if (tid == 0) {
        double mu = sh[0] / (double)N_EL;
        double var = sh2[0] / (double)N_EL - mu * mu;
        g_stats[0] = (float)mu;
        g_stats[1] = (float)(1.0 / sqrt(var + 1e-6));
    }
}

// ===========================================================================
// K2b: normalize -> fp16, transpose into ynT[m][row].
// ===========================================================================
__global__ void __launch_bounds__(256) k2b_normT(const float* __restrict__ sc,
                                                  const float* __restrict__ bi) {
    __shared__ __half sh[64 * 65];
    int tid = threadIdx.x;
    int r0 = blockIdx.x * 64;
    float mu = g_stats[0], rs = g_stats[1];

    #pragma unroll
    for (int it = 0; it < 16; it++) {
        int idx = tid + it * 256;
        int r = idx >> 6, m = idx & 63;
        size_t gi = (size_t)(r0 + r) * 64 + m;
        float val = (g_y[gi] - mu) * rs * sc[gi] + bi[gi];
        sh[m * 65 + r] = __float2half(val);
    }
    __syncthreads();

    int w = tid >> 5, lane = tid & 31;
    #pragma unroll 1
    for (int m = w; m < 64; m += 8) {
        __half2 p;
        p.x = sh[m * 65 + lane * 2];
        p.y = sh[m * 65 + lane * 2 + 1];
        *((__half2*)(g_ynT + (size_t)m * 8192 + r0) + lane) = p;
    }
}

// ===========================================================================
// mma helpers (fp16 HMMA path)
// ===========================================================================
__device__ __forceinline__ void ldsm4(uint32_t& r0, uint32_t& r1, uint32_t& r2,
                                      uint32_t& r3, const void* p) {
    uint32_t a = (uint32_t)__cvta_generic_to_shared(p);
    asm volatile("ldmatrix.sync.aligned.m8n8.x4.shared.b16 {%0,%1,%2,%3}, [%4];"
                 : "=r"(r0), "=r"(r1), "=r"(r2), "=r"(r3) : "r"(a));
}
__device__ __forceinline__ void ldsm4t(uint32_t& r0, uint32_t& r1, uint32_t& r2,
                                       uint32_t& r3, const void* p) {
    uint32_t a = (uint32_t)__cvta_generic_to_shared(p);
    asm volatile("ldmatrix.sync.aligned.m8n8.x4.trans.shared.b16 {%0,%1,%2,%3}, [%4];"
                 : "=r"(r0), "=r"(r1), "=r"(r2), "=r"(r3) : "r"(a));
}
__device__ __forceinline__ void mma16816(float* d, uint32_t a0, uint32_t a1,
                                         uint32_t a2, uint32_t a3,
                                         uint32_t b0, uint32_t b1) {
    asm volatile(
        "mma.sync.aligned.m16n8k16.row.col.f32.f16.f16.f32 "
        "{%0,%1,%2,%3}, {%4,%5,%6,%7}, {%8,%9}, {%0,%1,%2,%3};"
        : "+f"(d[0]), "+f"(d[1]), "+f"(d[2]), "+f"(d[3])
        : "r"(a0), "r"(a1), "r"(a2), "r"(a3), "r"(b0), "r"(b1));
}

// ===========================================================================
// K3: out_part[n,m] = sum_k ynT[m,k]*Co[k,n] via mma.sync fp16.
// Grid (64 col-tiles x 128 n, 4 k-splits x 2048). 128 threads (4 warps),
// 3 CTAs/SM. Warp tile m64 x n32 (warp = n-group): B read exactly once,
// A read 4x (16 KB + 8 KB reads/chunk). Double-buffered smem, 1-chunk
// register prefetch of the fp32 Co tile (cvt to fp16 on store).
// ===========================================================================
__global__ void __launch_bounds__(128, 3) k3_gemm(const float* __restrict__ Co) {
    __shared__ __align__(16) __half co_s[2][KC][CO_LD];    // 17.4 KB
    __shared__ __align__(16) __half yn_s[2][64][YN_LD];    // 10.2 KB
    int tid = threadIdx.x, w = tid >> 5, lane = tid & 31;
    int colbase = blockIdx.x * 128;
    int k_org = blockIdx.y * KQ;

    // staging maps: Co 32x128 fp32 -> 128B/thread (8 float4);
    //               yn 64x32 fp16 -> 32B/thread (2 uint4)
    int ck = tid >> 2, cf4 = tid & 3;            // Co row, float4 lane
    int ym = tid >> 1, yseg = (tid & 1) * 16;    // yn row, k offset
    const float4* cptr = (const float4*)(Co + (size_t)(k_org + ck) * 8192 + colbase) + cf4;
    const __half* yptr = g_ynT + (size_t)ym * 8192 + k_org + yseg;

    float4 cr[8];
    uint4  yr[2];

    auto LOAD = [&](int ch) {
        const float4* p = cptr + (size_t)ch * KC * 2048;
        #pragma unroll
        for (int j = 0; j < 8; j++) cr[j] = __ldg(p + j * 4);
        const uint4* q = (const uint4*)(yptr + ch * KC);
        yr[0] = __ldg(q); yr[1] = __ldg(q + 1);
    };
    auto STORE = [&](int buf) {
        #pragma unroll
        for (int j = 0; j < 8; j++) {
            uint32_t p0, p1;
            asm("cvt.rn.f16x2.f32 %0, %1, %2;" : "=r"(p0) : "f"(cr[j].y), "f"(cr[j].x));
            asm("cvt.rn.f16x2.f32 %0, %1, %2;" : "=r"(p1) : "f"(cr[j].w), "f"(cr[j].z));
            *(uint2*)&co_s[buf][ck][(cf4 + j * 4) * 4] = make_uint2(p0, p1);
        }
        uint4* yd = (uint4*)&yn_s[buf][ym][yseg];
        yd[0] = yr[0]; yd[1] = yr[1];
    };

    float d[4][4][4];                            // [mt][nt][v]
    #pragma unroll
    for (int mt = 0; mt < 4; mt++)
        #pragma unroll
        for (int nt = 0; nt < 4; nt++)
            #pragma unroll
            for (int v = 0; v < 4; v++) d[mt][nt][v] = 0.f;

    int q = lane >> 3, r8 = lane & 7;
    int arow = (q & 1) * 8 + r8, acol = (q >> 1) * 8;

    LOAD(0); STORE(0);
    LOAD(1);
    __syncthreads();

    #pragma unroll 1
    for (int ch = 0; ch < NCH; ch++) {
        int buf = ch & 1;
        #pragma unroll
        for (int kk = 0; kk < 2; kk++) {
            uint32_t b[8];
            ldsm4t(b[0], b[1], b[2], b[3], &co_s[buf][kk * 16 + arow][w * 32 + acol]);
            ldsm4t(b[4], b[5], b[6], b[7], &co_s[buf][kk * 16 + arow][w * 32 + 16 + acol]);
            #pragma unroll
            for (int mt = 0; mt < 4; mt++) {
                uint32_t a0, a1, a2, a3;
                ldsm4(a0, a1, a2, a3, &yn_s[buf][mt * 16 + arow][kk * 16 + acol]);
                mma16816(d[mt][0], a0, a1, a2, a3, b[0], b[1]);
                mma16816(d[mt][1], a0, a1, a2, a3, b[2], b[3]);
                mma16816(d[mt][2], a0, a1, a2, a3, b[4], b[5]);
                mma16816(d[mt][3], a0, a1, a2, a3, b[6], b[7]);
            }
        }
        __syncthreads();
        if (ch + 1 < NCH) {
            STORE(buf ^ 1);
            if (ch + 2 < NCH) LOAD(ch + 2);
        }
        __syncthreads();
    }

    // epilogue: write k-split partial
    float* pb = g_part + (size_t)blockIdx.y * N_EL;
    int er = lane >> 2, ec = (lane & 3) * 2;
    #pragma unroll
    for (int mt = 0; mt < 4; mt++) {
        #pragma unroll
        for (int nt = 0; nt < 4; nt++) {
            int n = colbase + w * 32 + nt * 8 + ec;
            int m = mt * 16 + er;
            pb[(size_t)n * 64 + m]           = d[mt][nt][0];
            pb[(size_t)(n + 1) * 64 + m]     = d[mt][nt][1];
            pb[(size_t)n * 64 + m + 8]       = d[mt][nt][2];
            pb[(size_t)(n + 1) * 64 + m + 8] = d[mt][nt][3];
        }
    }
}

// ===========================================================================
// K4: out = sum of 4 k-split partials (float4)
// ===========================================================================
__global__ void __launch_bounds__(256) k4_reduce(float* __restrict__ out) {
    int idx = blockIdx.x * 256 + threadIdx.x;
    float4 a = ((const float4*)g_part)[idx];
    #pragma unroll
    for (int s = 1; s < KSPLIT; s++) {
        float4 b = ((const float4*)(g_part + (size_t)s * N_EL))[idx];
        a.x += b.x; a.y += b.y; a.z += b.z; a.w += b.w;
    }
    ((float4*)out)[idx] = a;
}

extern "C" void kernel_launch(void* const* d_in, const int* in_sizes, int n_in,
                              void* d_out, int out_size) {
    const float* x  = (const float*)d_in[0];
    const float* Wi = (const float*)d_in[1];
    const float* sc = (const float*)d_in[2];
    const float* bi = (const float*)d_in[3];
    const float* Co = (const float*)d_in[4];
    float* out = (float*)d_out;

    k1_capsule<<<N_CI, 256>>>(x, Wi);
    k2_stats<<<1, 256>>>();
    k2b_normT<<<128, 256>>>(sc, bi);
    dim3 g3(64, KSPLIT);
    k3_gemm<<<g3, 128>>>(Co);
    k4_reduce<<<512, 256>>>(out);
}

// round 10
// speedup vs baseline: 1.8821x; 1.1469x over previous
#include <cuda_runtime.h>
#include <cuda_fp16.h>
#include <math.h>
#include <stdint.h>

#define N_CI    2048
#define N_EL    524288          // 8192 * 64
#define KSPLIT  8
#define KQ      1024            // K per split
#define KC      32
#define NCH     (KQ / KC)       // 32 chunks
#define CO_LD   136             // Co tile row stride (fp16 elems)
#define YN_LD   40              // ynT tile row stride

__device__ __align__(16) float g_y[N_EL];
__device__ __align__(16) __half g_ynT[64 * 8192];         // [m][row], fp16
__device__ __align__(16) float g_part[KSPLIT * N_EL];
__device__ float g_psum[N_CI];
__device__ float g_psq[N_CI];
__device__ float g_stats[2];

__device__ __forceinline__ float gelu_tanh(float v) {
    const float c = 0.7978845608028654f;
    float t = tanhf(c * (v + 0.044715f * v * v * v));
    return 0.5f * v * (1.0f + t);
}

// ===========================================================================
// K1: y[i,l,j] = sum_{k,m} Wi[i,j,k,l,m] * x[i,m,k]; gelu; LN partials.
// 2 j's interleaved -> 16 outstanding LDG.128 between shfl reductions.
// ===========================================================================
__global__ void __launch_bounds__(256) k1_capsule(const float* __restrict__ x,
                                                  const float* __restrict__ Wi) {
    __shared__ float4 xs4[64];
    __shared__ float s_sum, s_sq;
    int tid = threadIdx.x;
    int i = blockIdx.x;
    if (tid == 0) { s_sum = 0.f; s_sq = 0.f; }
    {
        int k = tid >> 2, m = tid & 3;
        ((float*)xs4)[tid] = x[(size_t)i * 256 + m * 64 + k];
    }
    __syncthreads();

    int w = tid >> 5, lane = tid & 31;
    int l = lane & 3, kq = lane >> 2;
    const float4* wbase = (const float4*)(Wi + (size_t)i * 65536);
    float ls = 0.f, ls2 = 0.f;

    #pragma unroll 1
    for (int jj = 0; jj < 8; jj += 2) {
        int j0 = w * 8 + jj;
        const float4* wp0 = wbase + (size_t)j0 * 256 + lane;
        const float4* wp1 = wp0 + 256;
        float acc0 = 0.f, acc1 = 0.f;
        #pragma unroll
        for (int r = 0; r < 8; r++) {
            float4 wv0 = wp0[r * 32];
            float4 wv1 = wp1[r * 32];
            float4 xv = xs4[r * 8 + kq];
            acc0 = fmaf(wv0.x, xv.x, acc0);
            acc0 = fmaf(wv0.y, xv.y, acc0);
            acc0 = fmaf(wv0.z, xv.z, acc0);
            acc0 = fmaf(wv0.w, xv.w, acc0);
            acc1 = fmaf(wv1.x, xv.x, acc1);
            acc1 = fmaf(wv1.y, xv.y, acc1);
            acc1 = fmaf(wv1.z, xv.z, acc1);
            acc1 = fmaf(wv1.w, xv.w, acc1);
        }
        acc0 += __shfl_xor_sync(0xffffffffu, acc0, 4);
        acc0 += __shfl_xor_sync(0xffffffffu, acc0, 8);
        acc0 += __shfl_xor_sync(0xffffffffu, acc0, 16);
        acc1 += __shfl_xor_sync(0xffffffffu, acc1, 4);
        acc1 += __shfl_xor_sync(0xffffffffu, acc1, 8);
        acc1 += __shfl_xor_sync(0xffffffffu, acc1, 16);
        float g0 = gelu_tanh(acc0);
        float g1 = gelu_tanh(acc1);
        if (lane < 4) {
            g_y[((size_t)i * 4 + l) * 64 + j0]     = g0;
            g_y[((size_t)i * 4 + l) * 64 + j0 + 1] = g1;
            ls += g0 + g1;
            ls2 += g0 * g0 + g1 * g1;
        }
    }
    if (lane < 4) {
        atomicAdd(&s_sum, ls);
        atomicAdd(&s_sq, ls2);
    }
    __syncthreads();
    if (tid == 0) { g_psum[i] = s_sum; g_psq[i] = s_sq; }
}

// ===========================================================================
// K2: reduce partials -> mu, rsig (1 CTA, fp64)
// ===========================================================================
__global__ void k2_stats() {
    __shared__ double sh[256], sh2[256];
    int tid = threadIdx.x;
    double a = 0.0, b = 0.0;
    for (int i = tid; i < N_CI; i += 256) {
        a += (double)g_psum[i];
        b += (double)g_psq[i];
    }
    sh[tid] = a; sh2[tid] = b;
    __syncthreads();
    for (int s = 128; s > 0; s >>= 1) {
        if (tid < s) { sh[tid] += sh[tid + s]; sh2[tid] += sh2[tid + s]; }
        __syncthreads();
    }
    if (tid == 0) {
        double mu = sh[0] / (double)N_EL;
        double var = sh2[0] / (double)N_EL - mu * mu;
        g_stats[0] = (float)mu;
        g_stats[1] = (float)(1.0 / sqrt(var + 1e-6));
    }
}

// ===========================================================================
// K2b: normalize -> fp16, transpose into ynT[m][row].
// ===========================================================================
__global__ void __launch_bounds__(256) k2b_normT(const float* __restrict__ sc,
                                                  const float* __restrict__ bi) {
    __shared__ __half sh[64 * 65];
    int tid = threadIdx.x;
    int r0 = blockIdx.x * 64;
    float mu = g_stats[0], rs = g_stats[1];

    #pragma unroll
    for (int it = 0; it < 16; it++) {
        int idx = tid + it * 256;
        int r = idx >> 6, m = idx & 63;
        size_t gi = (size_t)(r0 + r) * 64 + m;
        float val = (g_y[gi] - mu) * rs * sc[gi] + bi[gi];
        sh[m * 65 + r] = __float2half(val);
    }
    __syncthreads();

    int w = tid >> 5, lane = tid & 31;
    #pragma unroll 1
    for (int m = w; m < 64; m += 8) {
        __half2 p;
        p.x = sh[m * 65 + lane * 2];
        p.y = sh[m * 65 + lane * 2 + 1];
        *((__half2*)(g_ynT + (size_t)m * 8192 + r0) + lane) = p;
    }
}

// ===========================================================================
// mma helpers (fp16 HMMA path)
// ===========================================================================
__device__ __forceinline__ void ldsm4(uint32_t& r0, uint32_t& r1, uint32_t& r2,
                                      uint32_t& r3, const void* p) {
    uint32_t a = (uint32_t)__cvta_generic_to_shared(p);
    asm volatile("ldmatrix.sync.aligned.m8n8.x4.shared.b16 {%0,%1,%2,%3}, [%4];"
                 : "=r"(r0), "=r"(r1), "=r"(r2), "=r"(r3) : "r"(a));
}
__device__ __forceinline__ void ldsm4t(uint32_t& r0, uint32_t& r1, uint32_t& r2,
                                       uint32_t& r3, const void* p) {
    uint32_t a = (uint32_t)__cvta_generic_to_shared(p);
    asm volatile("ldmatrix.sync.aligned.m8n8.x4.trans.shared.b16 {%0,%1,%2,%3}, [%4];"
                 : "=r"(r0), "=r"(r1), "=r"(r2), "=r"(r3) : "r"(a));
}
__device__ __forceinline__ void mma16816(float* d, uint32_t a0, uint32_t a1,
                                         uint32_t a2, uint32_t a3,
                                         uint32_t b0, uint32_t b1) {
    asm volatile(
        "mma.sync.aligned.m16n8k16.row.col.f32.f16.f16.f32 "
        "{%0,%1,%2,%3}, {%4,%5,%6,%7}, {%8,%9}, {%0,%1,%2,%3};"
        : "+f"(d[0]), "+f"(d[1]), "+f"(d[2]), "+f"(d[3])
        : "r"(a0), "r"(a1), "r"(a2), "r"(a3), "r"(b0), "r"(b1));
}

// ===========================================================================
// K3: out_part[n,m] = sum_k ynT[m,k]*Co[k,n] via mma.sync fp16.
// Grid (64 col-tiles x 128 n, 8 k-splits x 1024). 128 threads (4 warps),
// 3 CTAs/SM resident (512 CTAs -> 3.46/SM). Warp tile m64 x n32.
// Double-buffered smem, 1-chunk register prefetch (fp32 Co -> cvt fp16).
// ===========================================================================
__global__ void __launch_bounds__(128, 3) k3_gemm(const float* __restrict__ Co) {
    __shared__ __align__(16) __half co_s[2][KC][CO_LD];    // 17.4 KB
    __shared__ __align__(16) __half yn_s[2][64][YN_LD];    // 10.2 KB
    int tid = threadIdx.x, w = tid >> 5, lane = tid & 31;
    int colbase = blockIdx.x * 128;
    int k_org = blockIdx.y * KQ;

    int ck = tid >> 2, cf4 = tid & 3;
    int ym = tid >> 1, yseg = (tid & 1) * 16;
    const float4* cptr = (const float4*)(Co + (size_t)(k_org + ck) * 8192 + colbase) + cf4;
    const __half* yptr = g_ynT + (size_t)ym * 8192 + k_org + yseg;

    float4 cr[8];
    uint4  yr[2];

    auto LOAD = [&](int ch) {
        const float4* p = cptr + (size_t)ch * KC * 2048;
        #pragma unroll
        for (int j = 0; j < 8; j++) cr[j] = __ldg(p + j * 4);
        const uint4* q = (const uint4*)(yptr + ch * KC);
        yr[0] = __ldg(q); yr[1] = __ldg(q + 1);
    };
    auto STORE = [&](int buf) {
        #pragma unroll
        for (int j = 0; j < 8; j++) {
            uint32_t p0, p1;
            asm("cvt.rn.f16x2.f32 %0, %1, %2;" : "=r"(p0) : "f"(cr[j].y), "f"(cr[j].x));
            asm("cvt.rn.f16x2.f32 %0, %1, %2;" : "=r"(p1) : "f"(cr[j].w), "f"(cr[j].z));
            *(uint2*)&co_s[buf][ck][(cf4 + j * 4) * 4] = make_uint2(p0, p1);
        }
        uint4* yd = (uint4*)&yn_s[buf][ym][yseg];
        yd[0] = yr[0]; yd[1] = yr[1];
    };

    float d[4][4][4];
    #pragma unroll
    for (int mt = 0; mt < 4; mt++)
        #pragma unroll
        for (int nt = 0; nt < 4; nt++)
            #pragma unroll
            for (int v = 0; v < 4; v++) d[mt][nt][v] = 0.f;

    int q = lane >> 3, r8 = lane & 7;
    int arow = (q & 1) * 8 + r8, acol = (q >> 1) * 8;

    LOAD(0); STORE(0);
    LOAD(1);
    __syncthreads();

    #pragma unroll 1
    for (int ch = 0; ch < NCH; ch++) {
        int buf = ch & 1;
        #pragma unroll
        for (int kk = 0; kk < 2; kk++) {
            uint32_t b[8];
            ldsm4t(b[0], b[1], b[2], b[3], &co_s[buf][kk * 16 + arow][w * 32 + acol]);
            ldsm4t(b[4], b[5], b[6], b[7], &co_s[buf][kk * 16 + arow][w * 32 + 16 + acol]);
            #pragma unroll
            for (int mt = 0; mt < 4; mt++) {
                uint32_t a0, a1, a2, a3;
                ldsm4(a0, a1, a2, a3, &yn_s[buf][mt * 16 + arow][kk * 16 + acol]);
                mma16816(d[mt][0], a0, a1, a2, a3, b[0], b[1]);
                mma16816(d[mt][1], a0, a1, a2, a3, b[2], b[3]);
                mma16816(d[mt][2], a0, a1, a2, a3, b[4], b[5]);
                mma16816(d[mt][3], a0, a1, a2, a3, b[6], b[7]);
            }
        }
        __syncthreads();
        if (ch + 1 < NCH) {
            STORE(buf ^ 1);
            if (ch + 2 < NCH) LOAD(ch + 2);
        }
        __syncthreads();
    }

    // epilogue: write k-split partial
    float* pb = g_part + (size_t)blockIdx.y * N_EL;
    int er = lane >> 2, ec = (lane & 3) * 2;
    #pragma unroll
    for (int mt = 0; mt < 4; mt++) {
        #pragma unroll
        for (int nt = 0; nt < 4; nt++) {
            int n = colbase + w * 32 + nt * 8 + ec;
            int m = mt * 16 + er;
            pb[(size_t)n * 64 + m]           = d[mt][nt][0];
            pb[(size_t)(n + 1) * 64 + m]     = d[mt][nt][1];
            pb[(size_t)n * 64 + m + 8]       = d[mt][nt][2];
            pb[(size_t)(n + 1) * 64 + m + 8] = d[mt][nt][3];
        }
    }
}

// ===========================================================================
// K4: out = sum of 8 k-split partials (float4)
// ===========================================================================
__global__ void __launch_bounds__(256) k4_reduce(float* __restrict__ out) {
    int idx = blockIdx.x * 256 + threadIdx.x;
    float4 a = ((const float4*)g_part)[idx];
    #pragma unroll
    for (int s = 1; s < KSPLIT; s++) {
        float4 b = ((const float4*)(g_part + (size_t)s * N_EL))[idx];
        a.x += b.x; a.y += b.y; a.z += b.z; a.w += b.w;
    }
    ((float4*)out)[idx] = a;
}

extern "C" void kernel_launch(void* const* d_in, const int* in_sizes, int n_in,
                              void* d_out, int out_size) {
    const float* x  = (const float*)d_in[0];
    const float* Wi = (const float*)d_in[1];
    const float* sc = (const float*)d_in[2];
    const float* bi = (const float*)d_in[3];
    const float* Co = (const float*)d_in[4];
    float* out = (float*)d_out;

    k1_capsule<<<N_CI, 256>>>(x, Wi);
    k2_stats<<<1, 256>>>();
    k2b_normT<<<128, 256>>>(sc, bi);
    dim3 g3(64, KSPLIT);
    k3_gemm<<<g3, 128>>>(Co);
    k4_reduce<<<512, 256>>>(out);
}